// round 7
// baseline (speedup 1.0000x reference)
#include <cuda_runtime.h>
#include <cuda_fp16.h>

#define NN  100000
#define EE  1600000
#define INF 128
#define HH  64
typedef unsigned long long u64;

// ---- packed f32x2 ops (sm_103a) ----
#define FMA2(d,a,b,c) asm("fma.rn.f32x2 %0,%1,%2,%3;" : "=l"(d) : "l"(a), "l"(b), "l"(c))
#define ADD2(d,a,b)   asm("add.rn.f32x2 %0,%1,%2;"    : "=l"(d) : "l"(a), "l"(b))
#define MUL2(d,a,b)   asm("mul.rn.f32x2 %0,%1,%2;"    : "=l"(d) : "l"(a), "l"(b))
#define PACK2(d,x)    asm("mov.b64 %0,{%1,%1};" : "=l"(d) : "r"(__float_as_uint(x)))
#define PACKAB(d,a,b) asm("mov.b64 %0,{%1,%2};" : "=l"(d) : "r"(__float_as_uint(a)), "r"(__float_as_uint(b)))
#define UNPACK2(a,b,d) do { unsigned _ua,_ub; \
    asm("mov.b64 {%0,%1},%2;" : "=r"(_ua),"=r"(_ub) : "l"(d)); \
    a=__uint_as_float(_ua); b=__uint_as_float(_ub); } while(0)

__device__ __forceinline__ unsigned h2_to_u(__half2 h) {
    union { __half2 h; unsigned u; } c; c.h = h; return c.u;
}
__device__ __forceinline__ float2 u_to_f2(unsigned u) {
    union { unsigned u; __half2 h; } c; c.u = u; return __half22float2(c.h);
}

// ---------------- device scratch ----------------
__device__ float  g_ori[NN * HH];
__device__ float  g_t  [NN * HH];
__device__ __half g_xs [NN * HH];
__device__ float  g_dinv[NN];
__device__ int    g_cnt[NN];        // zero at load; k_fill drains it back to 0
__device__ int    g_ptr[NN + 1];
__device__ int    g_blk[128];
__device__ int    g_csr[EE];

// ---------------- CSR construction ----------------
__global__ void k_count(const int4* __restrict__ dst4, int e4) {
    int i = blockIdx.x * blockDim.x + threadIdx.x;
    if (i < e4) {
        int4 d = dst4[i];
        atomicAdd(&g_cnt[d.x], 1);
        atomicAdd(&g_cnt[d.y], 1);
        atomicAdd(&g_cnt[d.z], 1);
        atomicAdd(&g_cnt[d.w], 1);
    }
}

__global__ void k_scanA(int n) {
    __shared__ int s[1024];
    int tid = threadIdx.x;
    int i = blockIdx.x * 1024 + tid;
    int c = (i < n) ? g_cnt[i] : 0;
    s[tid] = c;
    __syncthreads();
    #pragma unroll
    for (int off = 1; off < 1024; off <<= 1) {
        int t = (tid >= off) ? s[tid - off] : 0;
        __syncthreads();
        s[tid] += t;
        __syncthreads();
    }
    if (i < n) {
        g_ptr[i] = s[tid] - c;
        g_dinv[i] = rsqrtf((float)(c + 1));
    }
    if (tid == 1023) g_blk[blockIdx.x] = s[1023];
}

// every block redundantly scans the <=128 block totals, then applies its offset
__global__ void k_scanC(int nb, int n) {
    __shared__ int pref[128];
    int t = threadIdx.x;
    if (t < 128) pref[t] = (t < nb) ? g_blk[t] : 0;
    __syncthreads();
    #pragma unroll
    for (int off = 1; off < 128; off <<= 1) {
        int v = 0;
        if (t < 128 && t >= off) v = pref[t - off];
        __syncthreads();
        if (t < 128) pref[t] += v;
        __syncthreads();
    }
    int b = blockIdx.x;
    int base = (b == 0) ? 0 : pref[b - 1];
    int i = b * 1024 + t;
    if (i < n) g_ptr[i] += base;
    if (b == 0 && t == 0) g_ptr[n] = pref[127];
}

__global__ void k_fill(const int4* __restrict__ src4, const int4* __restrict__ dst4, int e4) {
    int i = blockIdx.x * blockDim.x + threadIdx.x;
    if (i < e4) {
        int4 s = src4[i];
        int4 d = dst4[i];
        g_csr[g_ptr[d.x] + atomicSub(&g_cnt[d.x], 1) - 1] = s.x;
        g_csr[g_ptr[d.y] + atomicSub(&g_cnt[d.y], 1) - 1] = s.y;
        g_csr[g_ptr[d.z] + atomicSub(&g_cnt[d.z], 1) - 1] = s.z;
        g_csr[g_ptr[d.w] + atomicSub(&g_cnt[d.w], 1) - 1] = s.w;
    }
}

// ------------- register-tiled GEMM: out = A[n,K] @ W[K,64] (+bias) (*dinv) -------------
// 256 threads, M_TILE=128, thread tile 4 rows x 8 cols. W staged per 64-k chunk
// (keeps smem at 51.5KB for both K=64 and K=128 -> 4 CTAs/SM).
template<int K, bool BIAS, bool DINV, bool OUTH>
__global__ void __launch_bounds__(256, 4) k_gemm(const float* __restrict__ A,
                                                 const float* __restrict__ W,
                                                 const float* __restrict__ bias,
                                                 void* __restrict__ out, int n) {
    extern __shared__ char smem[];
    float* sA = (float*)smem;                         // [128][68] padded
    u64*   sW = (u64*)(smem + 128 * 68 * 4);          // [64][32] u64 (current chunk)
    float* sB = (float*)(sW + 64 * 32);               // [64]

    int t = threadIdx.x;
    int R0 = blockIdx.x * 128;
    if (BIAS && t < HH) sB[t] = bias[t];

    u64 acc[4][4];
    #pragma unroll
    for (int i = 0; i < 4; i++)
        #pragma unroll
        for (int j = 0; j < 4; j++) acc[i][j] = 0ull;

    int rbase = t & 31;
    int cp = (t >> 5) * 4;

    constexpr int NCH = K / 64;
    #pragma unroll
    for (int kc = 0; kc < NCH; kc++) {
        __syncthreads();
        // stage A chunk: 128 rows x 64 cols
        #pragma unroll
        for (int q = 0; q < 8; q++) {
            int idx = t + q * 256;
            int row = idx >> 4, kq = idx & 15;
            float4 v = make_float4(0.f, 0.f, 0.f, 0.f);
            if (R0 + row < n)
                v = *(const float4*)(A + (size_t)(R0 + row) * K + kc * 64 + kq * 4);
            *(float4*)(sA + row * 68 + kq * 4) = v;
        }
        // stage W chunk: rows kc*64 .. kc*64+63 (64 x 16 float4)
        {
            const float4* W4 = (const float4*)W + kc * 64 * 16;
            float4* sW4 = (float4*)sW;
            #pragma unroll
            for (int q = 0; q < 4; q++) sW4[t + q * 256] = W4[t + q * 256];
        }
        __syncthreads();

        #pragma unroll
        for (int k4 = 0; k4 < 16; k4++) {
            float4 av[4];
            #pragma unroll
            for (int i = 0; i < 4; i++)
                av[i] = *(const float4*)(sA + (rbase + 32 * i) * 68 + k4 * 4);
            #pragma unroll
            for (int kk = 0; kk < 4; kk++) {
                int k = k4 * 4 + kk;
                ulonglong2 w0 = *(const ulonglong2*)(sW + k * 32 + cp);
                ulonglong2 w1 = *(const ulonglong2*)(sW + k * 32 + cp + 2);
                #pragma unroll
                for (int i = 0; i < 4; i++) {
                    float a = (kk == 0) ? av[i].x : (kk == 1) ? av[i].y
                            : (kk == 2) ? av[i].z : av[i].w;
                    u64 a2; PACK2(a2, a);
                    FMA2(acc[i][0], a2, w0.x, acc[i][0]);
                    FMA2(acc[i][1], a2, w0.y, acc[i][1]);
                    FMA2(acc[i][2], a2, w1.x, acc[i][2]);
                    FMA2(acc[i][3], a2, w1.y, acc[i][3]);
                }
            }
        }
    }

    // epilogue (in place on acc)
    if (BIAS) {
        #pragma unroll
        for (int i = 0; i < 4; i++)
            #pragma unroll
            for (int j = 0; j < 4; j++) {
                u64 b2; PACKAB(b2, sB[2 * (cp + j)], sB[2 * (cp + j) + 1]);
                ADD2(acc[i][j], acc[i][j], b2);
            }
    }
    #pragma unroll
    for (int i = 0; i < 4; i++) {
        int r = R0 + rbase + 32 * i;
        if (r >= n) continue;
        if (DINV) {
            u64 dv2; PACK2(dv2, g_dinv[r]);
            #pragma unroll
            for (int j = 0; j < 4; j++) MUL2(acc[i][j], acc[i][j], dv2);
        }
        if (OUTH) {
            uint4 hv;
            float a0, a1;
            UNPACK2(a0, a1, acc[i][0]); hv.x = h2_to_u(__float22half2_rn(make_float2(a0, a1)));
            UNPACK2(a0, a1, acc[i][1]); hv.y = h2_to_u(__float22half2_rn(make_float2(a0, a1)));
            UNPACK2(a0, a1, acc[i][2]); hv.z = h2_to_u(__float22half2_rn(make_float2(a0, a1)));
            UNPACK2(a0, a1, acc[i][3]); hv.w = h2_to_u(__float22half2_rn(make_float2(a0, a1)));
            *(uint4*)((__half*)out + (size_t)r * HH + cp * 2) = hv;
        } else {
            ulonglong2* o = (ulonglong2*)((u64*)out + (size_t)r * 32 + cp);
            o[0] = make_ulonglong2(acc[i][0], acc[i][1]);
            o[1] = make_ulonglong2(acc[i][2], acc[i][3]);
        }
    }
}

// ---- aggregation over fp16 xs (+optional fused residual+LN+ReLU) ----
template<bool FUSE>
__global__ void k_agg(const __half* __restrict__ xs, const float* __restrict__ cb,
                      const float* __restrict__ ori,
                      const float* __restrict__ lw, const float* __restrict__ lb,
                      float* __restrict__ outp, int n) {
    int gi = blockIdx.x * blockDim.x + threadIdx.x;
    int row = gi >> 5, lane = gi & 31;
    if (row >= n) return;
    const unsigned* x2 = (const unsigned*)xs;
    float2 sf = u_to_f2(__ldg(x2 + (size_t)row * 32 + lane));
    float a0 = sf.x, a1 = sf.y;
    int e   = g_ptr[row];
    int end = g_ptr[row + 1];
    for (; e + 8 <= end; e += 8) {
        int s0 = g_csr[e],     s1 = g_csr[e + 1], s2 = g_csr[e + 2], s3 = g_csr[e + 3];
        int s4 = g_csr[e + 4], s5 = g_csr[e + 5], s6 = g_csr[e + 6], s7 = g_csr[e + 7];
        unsigned u0 = __ldg(x2 + (size_t)s0 * 32 + lane);
        unsigned u1 = __ldg(x2 + (size_t)s1 * 32 + lane);
        unsigned u2 = __ldg(x2 + (size_t)s2 * 32 + lane);
        unsigned u3 = __ldg(x2 + (size_t)s3 * 32 + lane);
        unsigned u4 = __ldg(x2 + (size_t)s4 * 32 + lane);
        unsigned u5 = __ldg(x2 + (size_t)s5 * 32 + lane);
        unsigned u6 = __ldg(x2 + (size_t)s6 * 32 + lane);
        unsigned u7 = __ldg(x2 + (size_t)s7 * 32 + lane);
        float2 f0 = u_to_f2(u0), f1 = u_to_f2(u1), f2 = u_to_f2(u2), f3 = u_to_f2(u3);
        float2 f4 = u_to_f2(u4), f5 = u_to_f2(u5), f6 = u_to_f2(u6), f7 = u_to_f2(u7);
        a0 += ((f0.x + f1.x) + (f2.x + f3.x)) + ((f4.x + f5.x) + (f6.x + f7.x));
        a1 += ((f0.y + f1.y) + (f2.y + f3.y)) + ((f4.y + f5.y) + (f6.y + f7.y));
    }
    if (e + 4 <= end) {
        int s0 = g_csr[e], s1 = g_csr[e + 1], s2 = g_csr[e + 2], s3 = g_csr[e + 3];
        unsigned u0 = __ldg(x2 + (size_t)s0 * 32 + lane);
        unsigned u1 = __ldg(x2 + (size_t)s1 * 32 + lane);
        unsigned u2 = __ldg(x2 + (size_t)s2 * 32 + lane);
        unsigned u3 = __ldg(x2 + (size_t)s3 * 32 + lane);
        float2 f0 = u_to_f2(u0), f1 = u_to_f2(u1), f2 = u_to_f2(u2), f3 = u_to_f2(u3);
        a0 += (f0.x + f1.x) + (f2.x + f3.x);
        a1 += (f0.y + f1.y) + (f2.y + f3.y);
        e += 4;
    }
    for (; e < end; e++) {
        float2 f = u_to_f2(__ldg(x2 + (size_t)g_csr[e] * 32 + lane));
        a0 += f.x;
        a1 += f.y;
    }
    float dv = g_dinv[row];
    float h0 = fmaf(a0, dv, cb[2 * lane]);
    float h1 = fmaf(a1, dv, cb[2 * lane + 1]);
    if (FUSE) {
        u64 ov = __ldg((const u64*)ori + (size_t)row * 32 + lane);
        float o0, o1; UNPACK2(o0, o1, ov);
        float x0 = h0 + o0, x1 = h1 + o1;
        float s = x0 + x1;
        #pragma unroll
        for (int off = 16; off; off >>= 1) s += __shfl_xor_sync(0xffffffffu, s, off);
        float mu = s * (1.0f / 64.0f);
        float d0 = x0 - mu, d1 = x1 - mu;
        float q = d0 * d0 + d1 * d1;
        #pragma unroll
        for (int off = 16; off; off >>= 1) q += __shfl_xor_sync(0xffffffffu, q, off);
        float r = rsqrtf(q * (1.0f / 64.0f) + 1e-5f);
        float y0 = fmaxf(fmaf(d0 * r, lw[2 * lane],     lb[2 * lane]),     0.f);
        float y1 = fmaxf(fmaf(d1 * r, lw[2 * lane + 1], lb[2 * lane + 1]), 0.f);
        u64 o; PACKAB(o, y0, y1);
        ((u64*)outp)[(size_t)row * 32 + lane] = o;
    } else {
        u64 o; PACKAB(o, h0, h1);
        ((u64*)outp)[(size_t)row * 32 + lane] = o;
    }
}

// ---------------- launcher ----------------
extern "C" void kernel_launch(void* const* d_in, const int* in_sizes, int n_in,
                              void* d_out, int out_size) {
    const float* in_feat = (const float*)d_in[0];
    const int*   ei      = (const int*)  d_in[1];
    const float* lin_w   = (const float*)d_in[2];
    const float* lin_b   = (const float*)d_in[3];
    const float* conv_w  = (const float*)d_in[4];
    const float* conv_b  = (const float*)d_in[5];
    const float* ln_w    = (const float*)d_in[6];
    const float* ln_b    = (const float*)d_in[7];
    float* out = (float*)d_out;

    int n = in_sizes[0] / INF;
    int e = in_sizes[1] / 2;
    const int* src = ei;
    const int* dst = ei + e;
    int e4 = e / 4;
    int nb = (n + 1023) / 1024;

    float  *p_ori, *p_t;
    __half *p_xs;
    cudaGetSymbolAddress((void**)&p_ori, g_ori);
    cudaGetSymbolAddress((void**)&p_t,   g_t);
    cudaGetSymbolAddress((void**)&p_xs,  g_xs);

    const int SM_GEMM = 128 * 68 * 4 + 64 * 32 * 8 + 64 * 4;  // 51456 (both K)
    cudaFuncSetAttribute(k_gemm<INF, true,  false, false>, cudaFuncAttributeMaxDynamicSharedMemorySize, SM_GEMM);
    cudaFuncSetAttribute(k_gemm<HH,  false, true,  true >, cudaFuncAttributeMaxDynamicSharedMemorySize, SM_GEMM);

    int gmm = (n + 127) / 128;
    int gwp = (n * 32 + 255) / 256;

    // Launch order keeps conv GEMM at index 3 (ncu's captured launch).
    k_count<<<(e4 + 255) / 256, 256>>>((const int4*)dst, e4);                        // 0
    k_scanA<<<nb, 1024>>>(n);                                                        // 1
    k_gemm<INF, true, false, false><<<gmm, 256, SM_GEMM>>>(in_feat, lin_w, lin_b, p_ori, n);  // 2
    k_gemm<HH, false, true, true><<<gmm, 256, SM_GEMM>>>(p_ori, conv_w, nullptr, p_xs, n);    // 3 <- profiled
    k_scanC<<<nb, 1024>>>(nb, n);                                                    // 4
    k_fill <<<(e4 + 255) / 256, 256>>>((const int4*)src, (const int4*)dst, e4);      // 5

    // prop 0
    k_agg<true><<<gwp, 256>>>(p_xs, conv_b, p_ori, ln_w + 1 * HH, ln_b + 1 * HH, p_t, n);
    // prop 1
    k_gemm<HH, false, true, true><<<gmm, 256, SM_GEMM>>>(p_t, conv_w, nullptr, p_xs, n);
    k_agg<true><<<gwp, 256>>>(p_xs, conv_b, p_ori, ln_w + 2 * HH, ln_b + 2 * HH, p_t, n);
    // prop 2 (final -> d_out)
    k_gemm<HH, false, true, true><<<gmm, 256, SM_GEMM>>>(p_t, conv_w, nullptr, p_xs, n);
    k_agg<false><<<gwp, 256>>>(p_xs, conv_b, nullptr, nullptr, nullptr, out, n);
}

// round 8
// speedup vs baseline: 1.0952x; 1.0952x over previous
#include <cuda_runtime.h>
#include <cuda_fp16.h>

#define NN  100000
#define EE  1600000
#define INF 128
#define HH  64
typedef unsigned long long u64;

// ---- packed f32x2 ops (sm_103a) ----
#define FMA2(d,a,b,c) asm("fma.rn.f32x2 %0,%1,%2,%3;" : "=l"(d) : "l"(a), "l"(b), "l"(c))
#define ADD2(d,a,b)   asm("add.rn.f32x2 %0,%1,%2;"    : "=l"(d) : "l"(a), "l"(b))
#define MUL2(d,a,b)   asm("mul.rn.f32x2 %0,%1,%2;"    : "=l"(d) : "l"(a), "l"(b))
#define PACK2(d,x)    asm("mov.b64 %0,{%1,%1};" : "=l"(d) : "r"(__float_as_uint(x)))
#define PACKAB(d,a,b) asm("mov.b64 %0,{%1,%2};" : "=l"(d) : "r"(__float_as_uint(a)), "r"(__float_as_uint(b)))
#define UNPACK2(a,b,d) do { unsigned _ua,_ub; \
    asm("mov.b64 {%0,%1},%2;" : "=r"(_ua),"=r"(_ub) : "l"(d)); \
    a=__uint_as_float(_ua); b=__uint_as_float(_ub); } while(0)

__device__ __forceinline__ unsigned h2_to_u(__half2 h) {
    union { __half2 h; unsigned u; } c; c.h = h; return c.u;
}
__device__ __forceinline__ float2 u_to_f2(unsigned u) {
    union { unsigned u; __half2 h; } c; c.u = u; return __half22float2(c.h);
}

// ---------------- device scratch ----------------
__device__ float  g_ori[NN * HH];
__device__ float  g_t  [NN * HH];
__device__ __half g_xs [NN * HH];
__device__ float  g_dinv[NN];
__device__ int    g_cnt[NN];        // zero at load; k_fill drains it back to 0
__device__ int    g_ptr[NN + 1];
__device__ int    g_blk[128];
__device__ int    g_csr[EE];

// ---------------- CSR construction ----------------
__global__ void k_count(const int4* __restrict__ dst4, int e4) {
    int i = blockIdx.x * blockDim.x + threadIdx.x;
    if (i < e4) {
        int4 d = dst4[i];
        atomicAdd(&g_cnt[d.x], 1);
        atomicAdd(&g_cnt[d.y], 1);
        atomicAdd(&g_cnt[d.z], 1);
        atomicAdd(&g_cnt[d.w], 1);
    }
}

__global__ void k_scanA(int n) {
    __shared__ int s[1024];
    int tid = threadIdx.x;
    int i = blockIdx.x * 1024 + tid;
    int c = (i < n) ? g_cnt[i] : 0;
    s[tid] = c;
    __syncthreads();
    #pragma unroll
    for (int off = 1; off < 1024; off <<= 1) {
        int t = (tid >= off) ? s[tid - off] : 0;
        __syncthreads();
        s[tid] += t;
        __syncthreads();
    }
    if (i < n) {
        g_ptr[i] = s[tid] - c;
        g_dinv[i] = rsqrtf((float)(c + 1));
    }
    if (tid == 1023) g_blk[blockIdx.x] = s[1023];
}

// every block redundantly scans the <=128 block totals, then applies its offset
__global__ void k_scanC(int nb, int n) {
    __shared__ int pref[128];
    int t = threadIdx.x;
    if (t < 128) pref[t] = (t < nb) ? g_blk[t] : 0;
    __syncthreads();
    #pragma unroll
    for (int off = 1; off < 128; off <<= 1) {
        int v = 0;
        if (t < 128 && t >= off) v = pref[t - off];
        __syncthreads();
        if (t < 128) pref[t] += v;
        __syncthreads();
    }
    int b = blockIdx.x;
    int base = (b == 0) ? 0 : pref[b - 1];
    int i = b * 1024 + t;
    if (i < n) g_ptr[i] += base;
    if (b == 0 && t == 0) g_ptr[n] = pref[127];
}

__global__ void k_fill(const int4* __restrict__ src4, const int4* __restrict__ dst4, int e4) {
    int i = blockIdx.x * blockDim.x + threadIdx.x;
    if (i < e4) {
        int4 s = src4[i];
        int4 d = dst4[i];
        g_csr[g_ptr[d.x] + atomicSub(&g_cnt[d.x], 1) - 1] = s.x;
        g_csr[g_ptr[d.y] + atomicSub(&g_cnt[d.y], 1) - 1] = s.y;
        g_csr[g_ptr[d.z] + atomicSub(&g_cnt[d.z], 1) - 1] = s.z;
        g_csr[g_ptr[d.w] + atomicSub(&g_cnt[d.w], 1) - 1] = s.w;
    }
}

// ------------- lin GEMM: ori = in[n,128] @ W[128,64] + b -------------
// 256 threads, (256,3): no reg cap (avoids the spill that regressed R7).
// W fully staged once (32KB); sA 34KB -> 67.8KB total, 3 CTAs/SM.
__global__ void __launch_bounds__(256, 3) k_lin(const float* __restrict__ A,
                                                const float* __restrict__ W,
                                                const float* __restrict__ bias,
                                                float* __restrict__ out, int n) {
    extern __shared__ char smem[];
    float* sA = (float*)smem;                         // [128][68]
    u64*   sW = (u64*)(smem + 128 * 68 * 4);          // [128][32]
    float* sB = (float*)(sW + INF * 32);              // [64]

    int t = threadIdx.x;
    int R0 = blockIdx.x * 128;

    {
        const float4* W4 = (const float4*)W;
        float4* sW4 = (float4*)sW;
        #pragma unroll
        for (int q = 0; q < 8; q++) sW4[t + q * 256] = W4[t + q * 256];
        if (t < HH) sB[t] = bias[t];
    }

    u64 acc[4][4];
    #pragma unroll
    for (int i = 0; i < 4; i++)
        #pragma unroll
        for (int j = 0; j < 4; j++) acc[i][j] = 0ull;

    int rbase = t & 31;
    int cp = (t >> 5) * 4;

    #pragma unroll
    for (int kc = 0; kc < 2; kc++) {
        __syncthreads();
        #pragma unroll
        for (int q = 0; q < 8; q++) {
            int idx = t + q * 256;
            int row = idx >> 4, kq = idx & 15;
            float4 v = make_float4(0.f, 0.f, 0.f, 0.f);
            if (R0 + row < n)
                v = *(const float4*)(A + (size_t)(R0 + row) * INF + kc * 64 + kq * 4);
            *(float4*)(sA + row * 68 + kq * 4) = v;
        }
        __syncthreads();

        #pragma unroll
        for (int k4 = 0; k4 < 16; k4++) {
            float4 av[4];
            #pragma unroll
            for (int i = 0; i < 4; i++)
                av[i] = *(const float4*)(sA + (rbase + 32 * i) * 68 + k4 * 4);
            #pragma unroll
            for (int kk = 0; kk < 4; kk++) {
                int k = kc * 64 + k4 * 4 + kk;
                ulonglong2 w0 = *(const ulonglong2*)(sW + k * 32 + cp);
                ulonglong2 w1 = *(const ulonglong2*)(sW + k * 32 + cp + 2);
                #pragma unroll
                for (int i = 0; i < 4; i++) {
                    float a = (kk == 0) ? av[i].x : (kk == 1) ? av[i].y
                            : (kk == 2) ? av[i].z : av[i].w;
                    u64 a2; PACK2(a2, a);
                    FMA2(acc[i][0], a2, w0.x, acc[i][0]);
                    FMA2(acc[i][1], a2, w0.y, acc[i][1]);
                    FMA2(acc[i][2], a2, w1.x, acc[i][2]);
                    FMA2(acc[i][3], a2, w1.y, acc[i][3]);
                }
            }
        }
    }

    #pragma unroll
    for (int i = 0; i < 4; i++) {
        int r = R0 + rbase + 32 * i;
        if (r >= n) continue;
        #pragma unroll
        for (int j = 0; j < 4; j++) {
            u64 b2; PACKAB(b2, sB[2 * (cp + j)], sB[2 * (cp + j) + 1]);
            ADD2(acc[i][j], acc[i][j], b2);
        }
        ulonglong2* o = (ulonglong2*)((u64*)out + (size_t)r * 32 + cp);
        o[0] = make_ulonglong2(acc[i][0], acc[i][1]);
        o[1] = make_ulonglong2(acc[i][2], acc[i][3]);
    }
}

// ------------- conv GEMM: xs = (t[n,64] @ W[64,64]) * dinv[row], fp16 out -------------
// (256,4): 64-reg cap OK for K=64 (verified 32.3us in R7).
__global__ void __launch_bounds__(256, 4) k_conv(const float* __restrict__ A,
                                                 const float* __restrict__ W,
                                                 __half* __restrict__ out, int n) {
    extern __shared__ char smem[];
    float* sA = (float*)smem;                         // [128][68]
    u64*   sW = (u64*)(smem + 128 * 68 * 4);          // [64][32]

    int t = threadIdx.x;
    int R0 = blockIdx.x * 128;

    {
        const float4* W4 = (const float4*)W;
        float4* sW4 = (float4*)sW;
        #pragma unroll
        for (int q = 0; q < 4; q++) sW4[t + q * 256] = W4[t + q * 256];
    }
    #pragma unroll
    for (int q = 0; q < 8; q++) {
        int idx = t + q * 256;
        int row = idx >> 4, kq = idx & 15;
        float4 v = make_float4(0.f, 0.f, 0.f, 0.f);
        if (R0 + row < n)
            v = *(const float4*)(A + (size_t)(R0 + row) * HH + kq * 4);
        *(float4*)(sA + row * 68 + kq * 4) = v;
    }
    __syncthreads();

    u64 acc[4][4];
    #pragma unroll
    for (int i = 0; i < 4; i++)
        #pragma unroll
        for (int j = 0; j < 4; j++) acc[i][j] = 0ull;

    int rbase = t & 31;
    int cp = (t >> 5) * 4;

    #pragma unroll
    for (int k4 = 0; k4 < 16; k4++) {
        float4 av[4];
        #pragma unroll
        for (int i = 0; i < 4; i++)
            av[i] = *(const float4*)(sA + (rbase + 32 * i) * 68 + k4 * 4);
        #pragma unroll
        for (int kk = 0; kk < 4; kk++) {
            int k = k4 * 4 + kk;
            ulonglong2 w0 = *(const ulonglong2*)(sW + k * 32 + cp);
            ulonglong2 w1 = *(const ulonglong2*)(sW + k * 32 + cp + 2);
            #pragma unroll
            for (int i = 0; i < 4; i++) {
                float a = (kk == 0) ? av[i].x : (kk == 1) ? av[i].y
                        : (kk == 2) ? av[i].z : av[i].w;
                u64 a2; PACK2(a2, a);
                FMA2(acc[i][0], a2, w0.x, acc[i][0]);
                FMA2(acc[i][1], a2, w0.y, acc[i][1]);
                FMA2(acc[i][2], a2, w1.x, acc[i][2]);
                FMA2(acc[i][3], a2, w1.y, acc[i][3]);
            }
        }
    }

    #pragma unroll
    for (int i = 0; i < 4; i++) {
        int r = R0 + rbase + 32 * i;
        if (r >= n) continue;
        u64 dv2; PACK2(dv2, g_dinv[r]);
        #pragma unroll
        for (int j = 0; j < 4; j++) MUL2(acc[i][j], acc[i][j], dv2);
        uint4 hv;
        float a0, a1;
        UNPACK2(a0, a1, acc[i][0]); hv.x = h2_to_u(__float22half2_rn(make_float2(a0, a1)));
        UNPACK2(a0, a1, acc[i][1]); hv.y = h2_to_u(__float22half2_rn(make_float2(a0, a1)));
        UNPACK2(a0, a1, acc[i][2]); hv.z = h2_to_u(__float22half2_rn(make_float2(a0, a1)));
        UNPACK2(a0, a1, acc[i][3]); hv.w = h2_to_u(__float22half2_rn(make_float2(a0, a1)));
        *(uint4*)(out + (size_t)r * HH + cp * 2) = hv;
    }
}

// ---- aggregation over fp16 xs (+optional fused residual+LN+ReLU) ----
template<bool FUSE>
__global__ void k_agg(const __half* __restrict__ xs, const float* __restrict__ cb,
                      const float* __restrict__ ori,
                      const float* __restrict__ lw, const float* __restrict__ lb,
                      float* __restrict__ outp, int n) {
    int gi = blockIdx.x * blockDim.x + threadIdx.x;
    int row = gi >> 5, lane = gi & 31;
    if (row >= n) return;
    const unsigned* x2 = (const unsigned*)xs;
    float2 sf = u_to_f2(__ldg(x2 + (size_t)row * 32 + lane));
    float a0 = sf.x, a1 = sf.y;
    int e   = g_ptr[row];
    int end = g_ptr[row + 1];
    for (; e + 8 <= end; e += 8) {
        int s0 = g_csr[e],     s1 = g_csr[e + 1], s2 = g_csr[e + 2], s3 = g_csr[e + 3];
        int s4 = g_csr[e + 4], s5 = g_csr[e + 5], s6 = g_csr[e + 6], s7 = g_csr[e + 7];
        unsigned u0 = __ldg(x2 + (size_t)s0 * 32 + lane);
        unsigned u1 = __ldg(x2 + (size_t)s1 * 32 + lane);
        unsigned u2 = __ldg(x2 + (size_t)s2 * 32 + lane);
        unsigned u3 = __ldg(x2 + (size_t)s3 * 32 + lane);
        unsigned u4 = __ldg(x2 + (size_t)s4 * 32 + lane);
        unsigned u5 = __ldg(x2 + (size_t)s5 * 32 + lane);
        unsigned u6 = __ldg(x2 + (size_t)s6 * 32 + lane);
        unsigned u7 = __ldg(x2 + (size_t)s7 * 32 + lane);
        float2 f0 = u_to_f2(u0), f1 = u_to_f2(u1), f2 = u_to_f2(u2), f3 = u_to_f2(u3);
        float2 f4 = u_to_f2(u4), f5 = u_to_f2(u5), f6 = u_to_f2(u6), f7 = u_to_f2(u7);
        a0 += ((f0.x + f1.x) + (f2.x + f3.x)) + ((f4.x + f5.x) + (f6.x + f7.x));
        a1 += ((f0.y + f1.y) + (f2.y + f3.y)) + ((f4.y + f5.y) + (f6.y + f7.y));
    }
    if (e + 4 <= end) {
        int s0 = g_csr[e], s1 = g_csr[e + 1], s2 = g_csr[e + 2], s3 = g_csr[e + 3];
        unsigned u0 = __ldg(x2 + (size_t)s0 * 32 + lane);
        unsigned u1 = __ldg(x2 + (size_t)s1 * 32 + lane);
        unsigned u2 = __ldg(x2 + (size_t)s2 * 32 + lane);
        unsigned u3 = __ldg(x2 + (size_t)s3 * 32 + lane);
        float2 f0 = u_to_f2(u0), f1 = u_to_f2(u1), f2 = u_to_f2(u2), f3 = u_to_f2(u3);
        a0 += (f0.x + f1.x) + (f2.x + f3.x);
        a1 += (f0.y + f1.y) + (f2.y + f3.y);
        e += 4;
    }
    for (; e < end; e++) {
        float2 f = u_to_f2(__ldg(x2 + (size_t)g_csr[e] * 32 + lane));
        a0 += f.x;
        a1 += f.y;
    }
    float dv = g_dinv[row];
    float h0 = fmaf(a0, dv, cb[2 * lane]);
    float h1 = fmaf(a1, dv, cb[2 * lane + 1]);
    if (FUSE) {
        u64 ov = __ldg((const u64*)ori + (size_t)row * 32 + lane);
        float o0, o1; UNPACK2(o0, o1, ov);
        float x0 = h0 + o0, x1 = h1 + o1;
        float s = x0 + x1;
        #pragma unroll
        for (int off = 16; off; off >>= 1) s += __shfl_xor_sync(0xffffffffu, s, off);
        float mu = s * (1.0f / 64.0f);
        float d0 = x0 - mu, d1 = x1 - mu;
        float q = d0 * d0 + d1 * d1;
        #pragma unroll
        for (int off = 16; off; off >>= 1) q += __shfl_xor_sync(0xffffffffu, q, off);
        float r = rsqrtf(q * (1.0f / 64.0f) + 1e-5f);
        float y0 = fmaxf(fmaf(d0 * r, lw[2 * lane],     lb[2 * lane]),     0.f);
        float y1 = fmaxf(fmaf(d1 * r, lw[2 * lane + 1], lb[2 * lane + 1]), 0.f);
        u64 o; PACKAB(o, y0, y1);
        ((u64*)outp)[(size_t)row * 32 + lane] = o;
    } else {
        u64 o; PACKAB(o, h0, h1);
        ((u64*)outp)[(size_t)row * 32 + lane] = o;
    }
}

// ---------------- launcher ----------------
extern "C" void kernel_launch(void* const* d_in, const int* in_sizes, int n_in,
                              void* d_out, int out_size) {
    const float* in_feat = (const float*)d_in[0];
    const int*   ei      = (const int*)  d_in[1];
    const float* lin_w   = (const float*)d_in[2];
    const float* lin_b   = (const float*)d_in[3];
    const float* conv_w  = (const float*)d_in[4];
    const float* conv_b  = (const float*)d_in[5];
    const float* ln_w    = (const float*)d_in[6];
    const float* ln_b    = (const float*)d_in[7];
    float* out = (float*)d_out;

    int n = in_sizes[0] / INF;
    int e = in_sizes[1] / 2;
    const int* src = ei;
    const int* dst = ei + e;
    int e4 = e / 4;
    int nb = (n + 1023) / 1024;

    float  *p_ori, *p_t;
    __half *p_xs;
    cudaGetSymbolAddress((void**)&p_ori, g_ori);
    cudaGetSymbolAddress((void**)&p_t,   g_t);
    cudaGetSymbolAddress((void**)&p_xs,  g_xs);

    const int SM_LIN  = 128 * 68 * 4 + INF * 32 * 8 + 64 * 4;  // 67840
    const int SM_CONV = 128 * 68 * 4 + HH  * 32 * 8;           // 51200
    cudaFuncSetAttribute(k_lin,  cudaFuncAttributeMaxDynamicSharedMemorySize, SM_LIN);
    cudaFuncSetAttribute(k_conv, cudaFuncAttributeMaxDynamicSharedMemorySize, SM_CONV);

    int gmm = (n + 127) / 128;
    int gwp = (n * 32 + 255) / 256;

    // Launch order: k_lin at index 3 (ncu's captured launch) to check for spills.
    k_count<<<(e4 + 255) / 256, 256>>>((const int4*)dst, e4);                        // 0
    k_scanA<<<nb, 1024>>>(n);                                                        // 1
    k_scanC<<<nb, 1024>>>(nb, n);                                                    // 2
    k_lin <<<gmm, 256, SM_LIN>>>(in_feat, lin_w, lin_b, p_ori, n);                   // 3 <- profiled
    k_conv<<<gmm, 256, SM_CONV>>>(p_ori, conv_w, p_xs, n);                           // 4
    k_fill<<<(e4 + 255) / 256, 256>>>((const int4*)src, (const int4*)dst, e4);       // 5

    // prop 0
    k_agg<true><<<gwp, 256>>>(p_xs, conv_b, p_ori, ln_w + 1 * HH, ln_b + 1 * HH, p_t, n);
    // prop 1
    k_conv<<<gmm, 256, SM_CONV>>>(p_t, conv_w, p_xs, n);
    k_agg<true><<<gwp, 256>>>(p_xs, conv_b, p_ori, ln_w + 2 * HH, ln_b + 2 * HH, p_t, n);
    // prop 2 (final -> d_out)
    k_conv<<<gmm, 256, SM_CONV>>>(p_t, conv_w, p_xs, n);
    k_agg<false><<<gwp, 256>>>(p_xs, conv_b, nullptr, nullptr, nullptr, out, n);
}